// round 1
// baseline (speedup 1.0000x reference)
#include <cuda_runtime.h>
#include <math.h>

// ---------------- static config ----------------
// B=2, C=128, H=W=T=32, OUT=256, WS=4, SHIFT=2, HEADS=8, hd=16, N=64, MLP=512
// tokens per batch = 32768, windows per batch = 512, total windows = 1024

// ---------------- device scratch ----------------
__device__ float g_t [2 * 32768 * 128];   // activations, token-major [b*32768+p][c]
__device__ float g_w [2 * 32768 * 128];   // window buffer / depthwise-conv output
__device__ float g_psum[1024 * 256];
__device__ float g_psqr[1024 * 256];
__device__ float g_bnsc[256];
__device__ float g_bnsh[256];

__device__ __forceinline__ int region(int q) { return q < 28 ? 0 : (q < 30 ? 1 : 2); }
__device__ __forceinline__ float gelu_exact(float v) {
    return 0.5f * v * (1.0f + erff(v * 0.70710678118654752f));
}

// ---------------- input transpose: x (B,C,32,32,32) -> g_t [b,p,c] ----------------
__global__ void k_tin(const float* __restrict__ x) {
    __shared__ float tile[32][33];
    int p0  = blockIdx.x * 32;
    int bc0 = blockIdx.y * 32;
    int lx = threadIdx.x, ly = threadIdx.y;
#pragma unroll
    for (int r = 0; r < 32; r += 8)
        tile[ly + r][lx] = x[(size_t)(bc0 + ly + r) * 32768 + p0 + lx];
    __syncthreads();
#pragma unroll
    for (int r = 0; r < 32; r += 8) {
        int p  = p0 + ly + r;
        int bc = bc0 + lx;
        g_t[(size_t)((bc >> 7) * 32768 + p) * 128 + (bc & 127)] = tile[lx][ly + r];
    }
}

// ---------------- LN1 + shift + window partition: g_t -> g_w ----------------
// one warp per destination window-token
__global__ void k_ln_part(const float* __restrict__ g, const float* __restrict__ b,
                          int shift) {
    int wt   = blockIdx.x * 8 + (threadIdx.x >> 5);
    int lane = threadIdx.x & 31;
    int widx = wt >> 6, n = wt & 63;
    int bb = widx >> 9;
    int wh = (widx >> 6) & 7, ww = (widx >> 3) & 7, wz = widx & 7;
    int a = n >> 4, b2 = (n >> 2) & 3, c2 = n & 3;
    int hh = (wh * 4 + a  + shift) & 31;
    int w2 = (ww * 4 + b2 + shift) & 31;
    int t2 = (wz * 4 + c2 + shift) & 31;
    const float4* src = (const float4*)(g_t + ((size_t)bb * 32768 + hh * 1024 + w2 * 32 + t2) * 128);
    float4 v = src[lane];
    float s = v.x + v.y + v.z + v.w;
    float q = v.x * v.x + v.y * v.y + v.z * v.z + v.w * v.w;
#pragma unroll
    for (int o = 16; o; o >>= 1) {
        s += __shfl_xor_sync(0xffffffffu, s, o);
        q += __shfl_xor_sync(0xffffffffu, q, o);
    }
    float mu   = s * (1.0f / 128.0f);
    float rstd = rsqrtf(q * (1.0f / 128.0f) - mu * mu + 1e-5f);
    float4 gg = ((const float4*)g)[lane];
    float4 bv = ((const float4*)b)[lane];
    float4 o4;
    o4.x = (v.x - mu) * rstd * gg.x + bv.x;
    o4.y = (v.y - mu) * rstd * gg.y + bv.y;
    o4.z = (v.z - mu) * rstd * gg.z + bv.z;
    o4.w = (v.w - mu) * rstd * gg.w + bv.w;
    ((float4*)(g_w + (size_t)wt * 128))[lane] = o4;
}

// ---------------- fused window attention: QKV + attn + proj + residual ----------------
// one CTA (256 threads) per window. dyn smem: Xs/Qs/Ks/Vs, each 64x132 fp32.
__global__ void __launch_bounds__(256) k_attn(
    const float* __restrict__ qw, const float* __restrict__ qb,
    const float* __restrict__ pw, const float* __restrict__ pb,
    const float* __restrict__ rpb, int shift) {
    extern __shared__ float sm[];
    float* Xs = sm;                 // input, later reused as O
    float* Qs = sm + 64 * 132;
    float* Ks = Qs + 64 * 132;
    float* Vs = Ks + 64 * 132;
    __shared__ int lbl[64];
    __shared__ int dstb[64];

    int tid  = threadIdx.x;
    int widx = blockIdx.x;
    int bb = widx >> 9, wh = (widx >> 6) & 7, ww = (widx >> 3) & 7, wz = widx & 7;

    // load window input
    const float* wsrc = g_w + (size_t)widx * 64 * 128;
#pragma unroll 4
    for (int r = 0; r < 32; r++) {
        int idx = tid + 256 * r;
        Xs[(idx >> 7) * 132 + (idx & 127)] = wsrc[idx];
    }
    if (tid < 64) {
        int n = tid;
        int a = n >> 4, b2 = (n >> 2) & 3, c2 = n & 3;
        int hs = wh * 4 + a, ws_ = ww * 4 + b2, ts = wz * 4 + c2;
        lbl[n] = region(hs) * 9 + region(ws_) * 3 + region(ts);
        int hh = (hs + shift) & 31, w2 = (ws_ + shift) & 31, t2 = (ts + shift) & 31;
        dstb[n] = ((bb << 15) + hh * 1024 + w2 * 32 + t2) * 128;
    }
    __syncthreads();

    // ---- QKV GEMM: 4 tokens per thread, 16-feature lanes ----
    int g = tid >> 4, fl = tid & 15;
    const float4* xr0 = (const float4*)(Xs + (4 * g + 0) * 132);
    const float4* xr1 = (const float4*)(Xs + (4 * g + 1) * 132);
    const float4* xr2 = (const float4*)(Xs + (4 * g + 2) * 132);
    const float4* xr3 = (const float4*)(Xs + (4 * g + 3) * 132);
#pragma unroll 1
    for (int k = 0; k < 24; k++) {
        int f = fl + 16 * k;
        float bia = qb[f];
        float a0 = bia, a1 = bia, a2 = bia, a3 = bia;
        const float4* wr = (const float4*)(qw + f * 128);
#pragma unroll 8
        for (int c4 = 0; c4 < 32; c4++) {
            float4 w4 = wr[c4];
            float4 x0 = xr0[c4], x1 = xr1[c4], x2 = xr2[c4], x3 = xr3[c4];
            a0 = fmaf(x0.x, w4.x, a0); a0 = fmaf(x0.y, w4.y, a0); a0 = fmaf(x0.z, w4.z, a0); a0 = fmaf(x0.w, w4.w, a0);
            a1 = fmaf(x1.x, w4.x, a1); a1 = fmaf(x1.y, w4.y, a1); a1 = fmaf(x1.z, w4.z, a1); a1 = fmaf(x1.w, w4.w, a1);
            a2 = fmaf(x2.x, w4.x, a2); a2 = fmaf(x2.y, w4.y, a2); a2 = fmaf(x2.z, w4.z, a2); a2 = fmaf(x2.w, w4.w, a2);
            a3 = fmaf(x3.x, w4.x, a3); a3 = fmaf(x3.y, w4.y, a3); a3 = fmaf(x3.z, w4.z, a3); a3 = fmaf(x3.w, w4.w, a3);
        }
        float sc = (f < 128) ? 0.25f : 1.0f;
        float* dst; int fo;
        if (f < 128)       { dst = Qs; fo = f; }
        else if (f < 256)  { dst = Ks; fo = f - 128; }
        else               { dst = Vs; fo = f - 256; }
        dst[(4 * g + 0) * 132 + fo] = a0 * sc;
        dst[(4 * g + 1) * 132 + fo] = a1 * sc;
        dst[(4 * g + 2) * 132 + fo] = a2 * sc;
        dst[(4 * g + 3) * 132 + fo] = a3 * sc;
    }
    __syncthreads();   // also releases Xs for reuse as O

    // ---- attention: row i owned by a 4-lane group; scores kept in registers ----
    {
        int i  = tid >> 2;
        int jb = (tid & 3) * 16;
        int ai = i >> 4, bi = (i >> 2) & 3, ci = i & 3;
        int li = lbl[i];
#pragma unroll 1
        for (int h = 0; h < 8; h++) {
            float q[16];
#pragma unroll
            for (int d = 0; d < 16; d++) q[d] = Qs[i * 132 + h * 16 + d];
            float sv[16];
            float mx = -1e30f;
#pragma unroll
            for (int jj = 0; jj < 16; jj++) {
                int j = jb + jj;
                const float* kr = Ks + j * 132 + h * 16;
                float acc = 0.0f;
#pragma unroll
                for (int d = 0; d < 16; d++) acc = fmaf(q[d], kr[d], acc);
                int aj = j >> 4, bj = (j >> 2) & 3, cj = j & 3;
                int ridx = (ai - aj + 3) * 49 + (bi - bj + 3) * 7 + (ci - cj + 3);
                acc += rpb[ridx * 8 + h];
                if (shift && (li != lbl[j])) acc -= 100.0f;
                sv[jj] = acc;
                mx = fmaxf(mx, acc);
            }
            mx = fmaxf(mx, __shfl_xor_sync(0xffffffffu, mx, 1));
            mx = fmaxf(mx, __shfl_xor_sync(0xffffffffu, mx, 2));
            float sum = 0.0f;
#pragma unroll
            for (int jj = 0; jj < 16; jj++) { sv[jj] = __expf(sv[jj] - mx); sum += sv[jj]; }
            sum += __shfl_xor_sync(0xffffffffu, sum, 1);
            sum += __shfl_xor_sync(0xffffffffu, sum, 2);
            float inv = 1.0f / sum;
#pragma unroll
            for (int d = 0; d < 16; d++) {
                float p = 0.0f;
#pragma unroll
                for (int jj = 0; jj < 16; jj++)
                    p = fmaf(sv[jj], Vs[(jb + jj) * 132 + h * 16 + d], p);
                p += __shfl_xor_sync(0xffffffffu, p, 1);
                p += __shfl_xor_sync(0xffffffffu, p, 2);
                if ((tid & 3) == 0) Xs[i * 132 + h * 16 + d] = p * inv;
            }
        }
    }
    __syncthreads();

    // ---- proj + residual scatter ----
#pragma unroll 1
    for (int k = 0; k < 8; k++) {
        int f = fl + 16 * k;
        float bia = pb[f];
        float a0 = bia, a1 = bia, a2 = bia, a3 = bia;
        const float4* wr = (const float4*)(pw + f * 128);
        const float4* o0 = (const float4*)(Xs + (4 * g + 0) * 132);
        const float4* o1 = (const float4*)(Xs + (4 * g + 1) * 132);
        const float4* o2 = (const float4*)(Xs + (4 * g + 2) * 132);
        const float4* o3 = (const float4*)(Xs + (4 * g + 3) * 132);
#pragma unroll 8
        for (int c4 = 0; c4 < 32; c4++) {
            float4 w4 = wr[c4];
            float4 x0 = o0[c4], x1 = o1[c4], x2 = o2[c4], x3 = o3[c4];
            a0 = fmaf(x0.x, w4.x, a0); a0 = fmaf(x0.y, w4.y, a0); a0 = fmaf(x0.z, w4.z, a0); a0 = fmaf(x0.w, w4.w, a0);
            a1 = fmaf(x1.x, w4.x, a1); a1 = fmaf(x1.y, w4.y, a1); a1 = fmaf(x1.z, w4.z, a1); a1 = fmaf(x1.w, w4.w, a1);
            a2 = fmaf(x2.x, w4.x, a2); a2 = fmaf(x2.y, w4.y, a2); a2 = fmaf(x2.z, w4.z, a2); a2 = fmaf(x2.w, w4.w, a2);
            a3 = fmaf(x3.x, w4.x, a3); a3 = fmaf(x3.y, w4.y, a3); a3 = fmaf(x3.z, w4.z, a3); a3 = fmaf(x3.w, w4.w, a3);
        }
        g_t[dstb[4 * g + 0] + f] += a0;
        g_t[dstb[4 * g + 1] + f] += a1;
        g_t[dstb[4 * g + 2] + f] += a2;
        g_t[dstb[4 * g + 3] + f] += a3;
    }
}

// ---------------- fused MLP: LN2 + fc1 + GELU + fc2 + residual ----------------
// one CTA per 64 consecutive tokens
__global__ void __launch_bounds__(256) k_mlp(
    const float* __restrict__ g2, const float* __restrict__ b2,
    const float* __restrict__ f1w, const float* __restrict__ f1b,
    const float* __restrict__ f2w, const float* __restrict__ f2b) {
    extern __shared__ float sm[];
    float* Xs = sm;                 // 64 x 132
    float* Hs = sm + 64 * 132;      // 64 x 516
    int tid = threadIdx.x;
    float* base = g_t + (size_t)blockIdx.x * 64 * 128;
#pragma unroll 4
    for (int r = 0; r < 32; r++) {
        int idx = tid + 256 * r;
        Xs[(idx >> 7) * 132 + (idx & 127)] = base[idx];
    }
    __syncthreads();
    // LN2 in place (4-lane group per token)
    {
        int i = tid >> 2, l = tid & 3;
        float s = 0.0f, q = 0.0f;
#pragma unroll
        for (int c = l * 32; c < l * 32 + 32; c++) { float v = Xs[i * 132 + c]; s += v; q += v * v; }
        s += __shfl_xor_sync(0xffffffffu, s, 1); s += __shfl_xor_sync(0xffffffffu, s, 2);
        q += __shfl_xor_sync(0xffffffffu, q, 1); q += __shfl_xor_sync(0xffffffffu, q, 2);
        float mu   = s * (1.0f / 128.0f);
        float rstd = rsqrtf(q * (1.0f / 128.0f) - mu * mu + 1e-5f);
#pragma unroll
        for (int c = l * 32; c < l * 32 + 32; c++) {
            float v = Xs[i * 132 + c];
            Xs[i * 132 + c] = (v - mu) * rstd * g2[c] + b2[c];
        }
    }
    __syncthreads();

    int g = tid >> 4, fl = tid & 15;
    const float4* xr0 = (const float4*)(Xs + (4 * g + 0) * 132);
    const float4* xr1 = (const float4*)(Xs + (4 * g + 1) * 132);
    const float4* xr2 = (const float4*)(Xs + (4 * g + 2) * 132);
    const float4* xr3 = (const float4*)(Xs + (4 * g + 3) * 132);
    // fc1 + gelu
#pragma unroll 1
    for (int k = 0; k < 32; k++) {
        int f = fl + 16 * k;
        float bia = f1b[f];
        float a0 = bia, a1 = bia, a2 = bia, a3 = bia;
        const float4* wr = (const float4*)(f1w + f * 128);
#pragma unroll 8
        for (int c4 = 0; c4 < 32; c4++) {
            float4 w4 = wr[c4];
            float4 x0 = xr0[c4], x1 = xr1[c4], x2 = xr2[c4], x3 = xr3[c4];
            a0 = fmaf(x0.x, w4.x, a0); a0 = fmaf(x0.y, w4.y, a0); a0 = fmaf(x0.z, w4.z, a0); a0 = fmaf(x0.w, w4.w, a0);
            a1 = fmaf(x1.x, w4.x, a1); a1 = fmaf(x1.y, w4.y, a1); a1 = fmaf(x1.z, w4.z, a1); a1 = fmaf(x1.w, w4.w, a1);
            a2 = fmaf(x2.x, w4.x, a2); a2 = fmaf(x2.y, w4.y, a2); a2 = fmaf(x2.z, w4.z, a2); a2 = fmaf(x2.w, w4.w, a2);
            a3 = fmaf(x3.x, w4.x, a3); a3 = fmaf(x3.y, w4.y, a3); a3 = fmaf(x3.z, w4.z, a3); a3 = fmaf(x3.w, w4.w, a3);
        }
        Hs[(4 * g + 0) * 516 + f] = gelu_exact(a0);
        Hs[(4 * g + 1) * 516 + f] = gelu_exact(a1);
        Hs[(4 * g + 2) * 516 + f] = gelu_exact(a2);
        Hs[(4 * g + 3) * 516 + f] = gelu_exact(a3);
    }
    __syncthreads();
    // fc2 + residual
    const float4* hr0 = (const float4*)(Hs + (4 * g + 0) * 516);
    const float4* hr1 = (const float4*)(Hs + (4 * g + 1) * 516);
    const float4* hr2 = (const float4*)(Hs + (4 * g + 2) * 516);
    const float4* hr3 = (const float4*)(Hs + (4 * g + 3) * 516);
#pragma unroll 1
    for (int k = 0; k < 8; k++) {
        int f = fl + 16 * k;
        float bia = f2b[f];
        float a0 = bia, a1 = bia, a2 = bia, a3 = bia;
        const float4* wr = (const float4*)(f2w + f * 512);
#pragma unroll 8
        for (int c4 = 0; c4 < 128; c4++) {
            float4 w4 = wr[c4];
            float4 x0 = hr0[c4], x1 = hr1[c4], x2 = hr2[c4], x3 = hr3[c4];
            a0 = fmaf(x0.x, w4.x, a0); a0 = fmaf(x0.y, w4.y, a0); a0 = fmaf(x0.z, w4.z, a0); a0 = fmaf(x0.w, w4.w, a0);
            a1 = fmaf(x1.x, w4.x, a1); a1 = fmaf(x1.y, w4.y, a1); a1 = fmaf(x1.z, w4.z, a1); a1 = fmaf(x1.w, w4.w, a1);
            a2 = fmaf(x2.x, w4.x, a2); a2 = fmaf(x2.y, w4.y, a2); a2 = fmaf(x2.z, w4.z, a2); a2 = fmaf(x2.w, w4.w, a2);
            a3 = fmaf(x3.x, w4.x, a3); a3 = fmaf(x3.y, w4.y, a3); a3 = fmaf(x3.z, w4.z, a3); a3 = fmaf(x3.w, w4.w, a3);
        }
        base[(4 * g + 0) * 128 + f] += a0;
        base[(4 * g + 1) * 128 + f] += a1;
        base[(4 * g + 2) * 128 + f] += a2;
        base[(4 * g + 3) * 128 + f] += a3;
    }
}

// ---------------- depthwise 3x3x3 conv: g_t -> g_w ----------------
// one CTA per (b, hh, ww) row of 32 tt-tokens; 128 threads (one per channel)
__global__ void k_dw(const float* __restrict__ w, const float* __restrict__ bias) {
    __shared__ float ws[128 * 27];
    int tid = threadIdx.x;
    for (int idx = tid; idx < 128 * 27; idx += 128) ws[idx] = w[idx];
    __syncthreads();
    int c = tid;
    float bv = bias[c];
    int rid = blockIdx.x;
    int bb = rid >> 10, hh = (rid >> 5) & 31, ww = rid & 31;
    const float* base = g_t + (size_t)bb * 32768 * 128;
    float* out = g_w + ((size_t)bb * 32768 + hh * 1024 + ww * 32) * 128;
    for (int tt = 0; tt < 32; tt++) {
        float acc = bv;
#pragma unroll
        for (int dh = -1; dh <= 1; dh++) {
            int h2 = hh + dh; if ((unsigned)h2 >= 32u) continue;
#pragma unroll
            for (int dw_ = -1; dw_ <= 1; dw_++) {
                int w2 = ww + dw_; if ((unsigned)w2 >= 32u) continue;
#pragma unroll
                for (int dt = -1; dt <= 1; dt++) {
                    int t2 = tt + dt; if ((unsigned)t2 >= 32u) continue;
                    acc = fmaf(base[(h2 * 1024 + w2 * 32 + t2) * 128 + c],
                               ws[c * 27 + (dh + 1) * 9 + (dw_ + 1) * 3 + (dt + 1)], acc);
                }
            }
        }
        out[tt * 128 + c] = acc;
    }
}

// ---------------- pointwise conv 128->256 GEMM + BN partials ----------------
__global__ void __launch_bounds__(256) k_pw(
    const float* __restrict__ w, const float* __restrict__ bias,
    float* __restrict__ out) {
    extern __shared__ float sm[];
    float* Xs = sm;                 // 64 x 132
    float* Zs = sm + 64 * 132;      // 64 x 261
    int tid = threadIdx.x;
    const float* base = g_w + (size_t)blockIdx.x * 64 * 128;
#pragma unroll 4
    for (int r = 0; r < 32; r++) {
        int idx = tid + 256 * r;
        Xs[(idx >> 7) * 132 + (idx & 127)] = base[idx];
    }
    __syncthreads();
    int g = tid >> 4, fl = tid & 15;
    const float4* xr0 = (const float4*)(Xs + (4 * g + 0) * 132);
    const float4* xr1 = (const float4*)(Xs + (4 * g + 1) * 132);
    const float4* xr2 = (const float4*)(Xs + (4 * g + 2) * 132);
    const float4* xr3 = (const float4*)(Xs + (4 * g + 3) * 132);
#pragma unroll 1
    for (int k = 0; k < 16; k++) {
        int o = fl + 16 * k;
        float bia = bias[o];
        float a0 = bia, a1 = bia, a2 = bia, a3 = bia;
        const float4* wr = (const float4*)(w + o * 128);
#pragma unroll 8
        for (int c4 = 0; c4 < 32; c4++) {
            float4 w4 = wr[c4];
            float4 x0 = xr0[c4], x1 = xr1[c4], x2 = xr2[c4], x3 = xr3[c4];
            a0 = fmaf(x0.x, w4.x, a0); a0 = fmaf(x0.y, w4.y, a0); a0 = fmaf(x0.z, w4.z, a0); a0 = fmaf(x0.w, w4.w, a0);
            a1 = fmaf(x1.x, w4.x, a1); a1 = fmaf(x1.y, w4.y, a1); a1 = fmaf(x1.z, w4.z, a1); a1 = fmaf(x1.w, w4.w, a1);
            a2 = fmaf(x2.x, w4.x, a2); a2 = fmaf(x2.y, w4.y, a2); a2 = fmaf(x2.z, w4.z, a2); a2 = fmaf(x2.w, w4.w, a2);
            a3 = fmaf(x3.x, w4.x, a3); a3 = fmaf(x3.y, w4.y, a3); a3 = fmaf(x3.z, w4.z, a3); a3 = fmaf(x3.w, w4.w, a3);
        }
        Zs[(4 * g + 0) * 261 + o] = a0;
        Zs[(4 * g + 1) * 261 + o] = a1;
        Zs[(4 * g + 2) * 261 + o] = a2;
        Zs[(4 * g + 3) * 261 + o] = a3;
    }
    __syncthreads();
    // coalesced store to out[b, o, p]
    {
        int warp = tid >> 5, lane = tid & 31;
        int token0 = blockIdx.x * 64;
        int bb = token0 >> 15, p0 = token0 & 32767;
        for (int o = warp; o < 256; o += 8) {
            float* op = out + (size_t)(bb * 256 + o) * 32768 + p0;
            op[lane]      = Zs[lane * 261 + o];
            op[lane + 32] = Zs[(lane + 32) * 261 + o];
        }
    }
    // deterministic per-CTA partial sums for BN
    {
        int o = tid;
        float s1 = 0.0f, s2 = 0.0f;
#pragma unroll 4
        for (int i = 0; i < 64; i++) { float z = Zs[i * 261 + o]; s1 += z; s2 += z * z; }
        g_psum[blockIdx.x * 256 + o] = s1;
        g_psqr[blockIdx.x * 256 + o] = s2;
    }
}

// ---------------- BN stats reduce (deterministic) ----------------
__global__ void k_bnred(const float* __restrict__ bng, const float* __restrict__ bnb) {
    int o = threadIdx.x;
    float s1 = 0.0f, s2 = 0.0f;
    for (int j = 0; j < 1024; j++) { s1 += g_psum[j * 256 + o]; s2 += g_psqr[j * 256 + o]; }
    float mu  = s1 * (1.0f / 65536.0f);
    float var = s2 * (1.0f / 65536.0f) - mu * mu;
    float sc  = bng[o] * rsqrtf(var + 1e-5f);
    g_bnsc[o] = sc;
    g_bnsh[o] = bnb[o] - mu * sc;
}

// ---------------- BN apply + ReLU (in place over d_out) ----------------
__global__ void k_bnap(float* __restrict__ out) {
    int idx4 = blockIdx.x * 256 + threadIdx.x;      // float4 index
    int o = ((idx4 * 4) >> 15) & 255;
    float sc = g_bnsc[o], sh = g_bnsh[o];
    float4 v = ((float4*)out)[idx4];
    v.x = fmaxf(v.x * sc + sh, 0.0f);
    v.y = fmaxf(v.y * sc + sh, 0.0f);
    v.z = fmaxf(v.z * sc + sh, 0.0f);
    v.w = fmaxf(v.w * sc + sh, 0.0f);
    ((float4*)out)[idx4] = v;
}

// ---------------- host launch ----------------
extern "C" void kernel_launch(void* const* d_in, const int* in_sizes, int n_in,
                              void* d_out, int out_size) {
    const float* x       = (const float*)d_in[0];
    const float* norm1_g = (const float*)d_in[1];
    const float* norm1_b = (const float*)d_in[2];
    const float* qkv_w   = (const float*)d_in[3];
    const float* qkv_b   = (const float*)d_in[4];
    const float* proj_w  = (const float*)d_in[5];
    const float* proj_b  = (const float*)d_in[6];
    const float* rpb     = (const float*)d_in[7];
    const float* norm2_g = (const float*)d_in[8];
    const float* norm2_b = (const float*)d_in[9];
    const float* fc1_w   = (const float*)d_in[10];
    const float* fc1_b   = (const float*)d_in[11];
    const float* fc2_w   = (const float*)d_in[12];
    const float* fc2_b   = (const float*)d_in[13];
    const float* dw_w    = (const float*)d_in[14];
    const float* dw_b    = (const float*)d_in[15];
    const float* pw_w    = (const float*)d_in[16];
    const float* pw_b    = (const float*)d_in[17];
    const float* bn_g    = (const float*)d_in[18];
    const float* bn_b    = (const float*)d_in[19];
    float* out = (float*)d_out;

    const int ASM = 4 * 64 * 132 * 4;                   // 135168
    const int MSM = 64 * 132 * 4 + 64 * 516 * 4;        // 165888
    const int PSM = 64 * 132 * 4 + 64 * 261 * 4;        // 100608
    cudaFuncSetAttribute(k_attn, cudaFuncAttributeMaxDynamicSharedMemorySize, ASM);
    cudaFuncSetAttribute(k_mlp,  cudaFuncAttributeMaxDynamicSharedMemorySize, MSM);
    cudaFuncSetAttribute(k_pw,   cudaFuncAttributeMaxDynamicSharedMemorySize, PSM);

    k_tin<<<dim3(1024, 8), dim3(32, 8)>>>(x);

    for (int l = 0; l < 4; l++) {
        int shift = (l & 1) ? 2 : 0;
        k_ln_part<<<8192, 256>>>(norm1_g + l * 128, norm1_b + l * 128, shift);
        k_attn<<<1024, 256, ASM>>>(qkv_w + l * 384 * 128, qkv_b + l * 384,
                                   proj_w + l * 128 * 128, proj_b + l * 128,
                                   rpb + l * 343 * 8, shift);
        k_mlp<<<1024, 256, MSM>>>(norm2_g + l * 128, norm2_b + l * 128,
                                  fc1_w + l * 512 * 128, fc1_b + l * 512,
                                  fc2_w + l * 128 * 512, fc2_b + l * 128);
    }

    k_dw<<<2048, 128>>>(dw_w, dw_b);
    k_pw<<<1024, 256, PSM>>>(pw_w, pw_b, out);
    k_bnred<<<1, 256>>>(bn_g, bn_b);
    k_bnap<<<16384, 256>>>(out);
}

// round 2
// speedup vs baseline: 3.1245x; 3.1245x over previous
#include <cuda_runtime.h>
#include <math.h>

// ---------------- static config ----------------
// B=2, C=128, H=W=T=32, OUT=256, WS=4, SHIFT=2, HEADS=8, hd=16, N=64, MLP=512

typedef unsigned long long u64;

// ---------------- device scratch ----------------
__device__ float g_t [2 * 32768 * 128];   // activations, token-major [b*32768+p][c]
__device__ float g_w [2 * 32768 * 128];   // window buffer / depthwise-conv output
__device__ float g_psum[1024 * 256];
__device__ float g_psqr[1024 * 256];
__device__ float g_bnsc[256];
__device__ float g_bnsh[256];

__device__ __forceinline__ int region(int q) { return q < 28 ? 0 : (q < 30 ? 1 : 2); }
__device__ __forceinline__ float gelu_exact(float v) {
    return 0.5f * v * (1.0f + erff(v * 0.70710678118654752f));
}

// ---------------- packed fp32x2 helpers ----------------
__device__ __forceinline__ void ffma2(u64 &d, u64 a, u64 b) {
    asm("fma.rn.f32x2 %0, %1, %2, %0;" : "+l"(d) : "l"(a), "l"(b));
}
__device__ __forceinline__ float2 unpk(u64 v) {
    float2 f; asm("mov.b64 {%0,%1}, %2;" : "=f"(f.x), "=f"(f.y) : "l"(v)); return f;
}
__device__ __forceinline__ float f2sum(u64 v) { float2 f = unpk(v); return f.x + f.y; }
__device__ __forceinline__ u64 fpack(float lo, float hi) {
    u64 r; asm("mov.b64 %0, {%1,%2};" : "=l"(r) : "f"(lo), "f"(hi)); return r;
}

// ---------------- cooperative weight-tile load: 64 rows x 128 ch -> Ws pitch 132 ----------------
__device__ __forceinline__ void load_w_tile(float* Ws, const float* __restrict__ gw,
                                            int ld, int tid) {
#pragma unroll
    for (int j = 0; j < 8; j++) {
        int i4 = tid + 256 * j;
        int row = i4 >> 5, col = i4 & 31;
        float4 v = ((const float4*)(gw + row * ld))[col];
        ((float4*)(Ws + row * 132))[col] = v;
    }
}

// ---------------- register-tiled packed GEMM: 4 tokens x 4 features, 128 channels ----------------
// X0 points at token row 0 of this thread's 4-token group (pitch XP floats).
// Ws is a 64-feature x 128-channel tile at pitch WP; thread's features are fl+{0,16,32,48}.
template<int XP, int WP>
__device__ __forceinline__ void gemm_tile(const float* __restrict__ X0,
                                          const float* __restrict__ Ws,
                                          int fl, u64 acc[4][4]) {
    const ulonglong2* x0 = (const ulonglong2*)(X0);
    const ulonglong2* x1 = (const ulonglong2*)(X0 + XP);
    const ulonglong2* x2 = (const ulonglong2*)(X0 + 2 * XP);
    const ulonglong2* x3 = (const ulonglong2*)(X0 + 3 * XP);
    const ulonglong2* w0 = (const ulonglong2*)(Ws + (fl     ) * WP);
    const ulonglong2* w1 = (const ulonglong2*)(Ws + (fl + 16) * WP);
    const ulonglong2* w2 = (const ulonglong2*)(Ws + (fl + 32) * WP);
    const ulonglong2* w3 = (const ulonglong2*)(Ws + (fl + 48) * WP);
#pragma unroll 4
    for (int c = 0; c < 32; c++) {
        ulonglong2 Xa = x0[c], Xb = x1[c], Xc = x2[c], Xd = x3[c];
        ulonglong2 Wa = w0[c], Wb = w1[c], Wc = w2[c], Wd = w3[c];
        ffma2(acc[0][0], Xa.x, Wa.x); ffma2(acc[0][0], Xa.y, Wa.y);
        ffma2(acc[1][0], Xb.x, Wa.x); ffma2(acc[1][0], Xb.y, Wa.y);
        ffma2(acc[2][0], Xc.x, Wa.x); ffma2(acc[2][0], Xc.y, Wa.y);
        ffma2(acc[3][0], Xd.x, Wa.x); ffma2(acc[3][0], Xd.y, Wa.y);
        ffma2(acc[0][1], Xa.x, Wb.x); ffma2(acc[0][1], Xa.y, Wb.y);
        ffma2(acc[1][1], Xb.x, Wb.x); ffma2(acc[1][1], Xb.y, Wb.y);
        ffma2(acc[2][1], Xc.x, Wb.x); ffma2(acc[2][1], Xc.y, Wb.y);
        ffma2(acc[3][1], Xd.x, Wb.x); ffma2(acc[3][1], Xd.y, Wb.y);
        ffma2(acc[0][2], Xa.x, Wc.x); ffma2(acc[0][2], Xa.y, Wc.y);
        ffma2(acc[1][2], Xb.x, Wc.x); ffma2(acc[1][2], Xb.y, Wc.y);
        ffma2(acc[2][2], Xc.x, Wc.x); ffma2(acc[2][2], Xc.y, Wc.y);
        ffma2(acc[3][2], Xd.x, Wc.x); ffma2(acc[3][2], Xd.y, Wc.y);
        ffma2(acc[0][3], Xa.x, Wd.x); ffma2(acc[0][3], Xa.y, Wd.y);
        ffma2(acc[1][3], Xb.x, Wd.x); ffma2(acc[1][3], Xb.y, Wd.y);
        ffma2(acc[2][3], Xc.x, Wd.x); ffma2(acc[2][3], Xc.y, Wd.y);
        ffma2(acc[3][3], Xd.x, Wd.x); ffma2(acc[3][3], Xd.y, Wd.y);
    }
}

// ---------------- input transpose: x (B,C,32,32,32) -> g_t [b,p,c] ----------------
__global__ void k_tin(const float* __restrict__ x) {
    __shared__ float tile[32][33];
    int p0  = blockIdx.x * 32;
    int bc0 = blockIdx.y * 32;
    int lx = threadIdx.x, ly = threadIdx.y;
#pragma unroll
    for (int r = 0; r < 32; r += 8)
        tile[ly + r][lx] = x[(size_t)(bc0 + ly + r) * 32768 + p0 + lx];
    __syncthreads();
#pragma unroll
    for (int r = 0; r < 32; r += 8) {
        int p  = p0 + ly + r;
        int bc = bc0 + lx;
        g_t[(size_t)((bc >> 7) * 32768 + p) * 128 + (bc & 127)] = tile[lx][ly + r];
    }
}

// ---------------- LN1 + shift + window partition: g_t -> g_w ----------------
__global__ void k_ln_part(const float* __restrict__ g, const float* __restrict__ b,
                          int shift) {
    int wt   = blockIdx.x * 8 + (threadIdx.x >> 5);
    int lane = threadIdx.x & 31;
    int widx = wt >> 6, n = wt & 63;
    int bb = widx >> 9;
    int wh = (widx >> 6) & 7, ww = (widx >> 3) & 7, wz = widx & 7;
    int a = n >> 4, b2 = (n >> 2) & 3, c2 = n & 3;
    int hh = (wh * 4 + a  + shift) & 31;
    int w2 = (ww * 4 + b2 + shift) & 31;
    int t2 = (wz * 4 + c2 + shift) & 31;
    const float4* src = (const float4*)(g_t + ((size_t)bb * 32768 + hh * 1024 + w2 * 32 + t2) * 128);
    float4 v = src[lane];
    float s = v.x + v.y + v.z + v.w;
    float q = v.x * v.x + v.y * v.y + v.z * v.z + v.w * v.w;
#pragma unroll
    for (int o = 16; o; o >>= 1) {
        s += __shfl_xor_sync(0xffffffffu, s, o);
        q += __shfl_xor_sync(0xffffffffu, q, o);
    }
    float mu   = s * (1.0f / 128.0f);
    float rstd = rsqrtf(q * (1.0f / 128.0f) - mu * mu + 1e-5f);
    float4 gg = ((const float4*)g)[lane];
    float4 bv = ((const float4*)b)[lane];
    float4 o4;
    o4.x = (v.x - mu) * rstd * gg.x + bv.x;
    o4.y = (v.y - mu) * rstd * gg.y + bv.y;
    o4.z = (v.z - mu) * rstd * gg.z + bv.z;
    o4.w = (v.w - mu) * rstd * gg.w + bv.w;
    ((float4*)(g_w + (size_t)wt * 128))[lane] = o4;
}

// ---------------- fused window attention ----------------
// one CTA (256 threads) per window. dyn smem: Xs/Qs/Ks/Vs/Ws, each 64x132 fp32.
__global__ void __launch_bounds__(256) k_attn(
    const float* __restrict__ qw, const float* __restrict__ qb,
    const float* __restrict__ pw, const float* __restrict__ pb,
    const float* __restrict__ rpb, int shift) {
    extern __shared__ float sm[];
    float* Xs = sm;                 // input / later O
    float* Qs = sm + 64 * 132;
    float* Ks = Qs + 64 * 132;
    float* Vs = Ks + 64 * 132;
    float* Ws = Vs + 64 * 132;
    __shared__ int lbl[64];
    __shared__ int dstb[64];

    int tid  = threadIdx.x;
    int widx = blockIdx.x;
    int bb = widx >> 9, wh = (widx >> 6) & 7, ww = (widx >> 3) & 7, wz = widx & 7;

    const float* wsrc = g_w + (size_t)widx * 64 * 128;
#pragma unroll 4
    for (int r = 0; r < 32; r++) {
        int idx = tid + 256 * r;
        Xs[(idx >> 7) * 132 + (idx & 127)] = wsrc[idx];
    }
    if (tid < 64) {
        int n = tid;
        int a = n >> 4, b2 = (n >> 2) & 3, c2 = n & 3;
        int hs = wh * 4 + a, ws_ = ww * 4 + b2, ts = wz * 4 + c2;
        lbl[n] = region(hs) * 9 + region(ws_) * 3 + region(ts);
        int hh = (hs + shift) & 31, w2 = (ws_ + shift) & 31, t2 = (ts + shift) & 31;
        dstb[n] = ((bb << 15) + hh * 1024 + w2 * 32 + t2) * 128;
    }

    int tg = tid >> 4, fl = tid & 15;
    const float* Xrow = Xs + 4 * tg * 132;

    // ---- QKV: 6 blocks of 64 features ----
#pragma unroll 1
    for (int blk = 0; blk < 6; blk++) {
        load_w_tile(Ws, qw + blk * 64 * 128, 128, tid);
        __syncthreads();
        u64 acc[4][4] = {};
        gemm_tile<132, 132>(Xrow, Ws, fl, acc);
        float* dst = (blk < 2) ? Qs : ((blk < 4) ? Ks : Vs);
        int fo = (blk & 1) * 64;
        float sc = (blk < 2) ? 0.25f : 1.0f;
#pragma unroll
        for (int t = 0; t < 4; t++)
#pragma unroll
            for (int j = 0; j < 4; j++) {
                int f = blk * 64 + fl + 16 * j;
                dst[(4 * tg + t) * 132 + fo + fl + 16 * j] = (f2sum(acc[t][j]) + qb[f]) * sc;
            }
        __syncthreads();
    }

    // ---- attention: row i owned by 4-lane group ----
    {
        int i  = tid >> 2;
        int jb = (tid & 3) * 16;
        int ai = i >> 4, bi = (i >> 2) & 3, ci = i & 3;
        int li = lbl[i];
        int ridx16[16];
        float mk[16];
#pragma unroll
        for (int jj = 0; jj < 16; jj++) {
            int j = jb + jj;
            int aj = j >> 4, bj = (j >> 2) & 3, cj = j & 3;
            ridx16[jj] = ((ai - aj + 3) * 49 + (bi - bj + 3) * 7 + (ci - cj + 3)) * 8;
            mk[jj] = (shift && (li != lbl[j])) ? -100.0f : 0.0f;
        }
#pragma unroll 1
        for (int h = 0; h < 8; h++) {
            const u64* qr = (const u64*)(Qs + i * 132 + h * 16);
            u64 q2[8];
#pragma unroll
            for (int d = 0; d < 8; d++) q2[d] = qr[d];
            float sv[16];
            float mx = -1e30f;
#pragma unroll
            for (int jj = 0; jj < 16; jj++) {
                const u64* kr = (const u64*)(Ks + (jb + jj) * 132 + h * 16);
                u64 a2 = 0;
#pragma unroll
                for (int d = 0; d < 8; d++) ffma2(a2, q2[d], kr[d]);
                float acc = f2sum(a2) + rpb[ridx16[jj] + h] + mk[jj];
                sv[jj] = acc;
                mx = fmaxf(mx, acc);
            }
            mx = fmaxf(mx, __shfl_xor_sync(0xffffffffu, mx, 1));
            mx = fmaxf(mx, __shfl_xor_sync(0xffffffffu, mx, 2));
            float sum = 0.0f;
#pragma unroll
            for (int jj = 0; jj < 16; jj++) { sv[jj] = __expf(sv[jj] - mx); sum += sv[jj]; }
            sum += __shfl_xor_sync(0xffffffffu, sum, 1);
            sum += __shfl_xor_sync(0xffffffffu, sum, 2);
            float inv = 1.0f / sum;
            u64 o2[8] = {};
#pragma unroll
            for (int jj = 0; jj < 16; jj++) {
                u64 s2 = fpack(sv[jj], sv[jj]);
                const u64* vr = (const u64*)(Vs + (jb + jj) * 132 + h * 16);
#pragma unroll
                for (int d = 0; d < 8; d++) ffma2(o2[d], s2, vr[d]);
            }
#pragma unroll
            for (int d = 0; d < 8; d++) {
                float2 f = unpk(o2[d]);
                f.x += __shfl_xor_sync(0xffffffffu, f.x, 1);
                f.x += __shfl_xor_sync(0xffffffffu, f.x, 2);
                f.y += __shfl_xor_sync(0xffffffffu, f.y, 1);
                f.y += __shfl_xor_sync(0xffffffffu, f.y, 2);
                if ((tid & 3) == 0) {
                    Xs[i * 132 + h * 16 + 2 * d]     = f.x * inv;
                    Xs[i * 132 + h * 16 + 2 * d + 1] = f.y * inv;
                }
            }
        }
    }

    // ---- proj + residual scatter: 2 blocks of 64 features ----
#pragma unroll 1
    for (int blk = 0; blk < 2; blk++) {
        load_w_tile(Ws, pw + blk * 64 * 128, 128, tid);
        __syncthreads();
        u64 acc[4][4] = {};
        gemm_tile<132, 132>(Xrow, Ws, fl, acc);
#pragma unroll
        for (int t = 0; t < 4; t++)
#pragma unroll
            for (int j = 0; j < 4; j++) {
                int f = blk * 64 + fl + 16 * j;
                g_t[dstb[4 * tg + t] + f] += f2sum(acc[t][j]) + pb[f];
            }
        __syncthreads();
    }
}

// ---------------- fused MLP: LN2 + fc1 + GELU + fc2 + residual ----------------
__global__ void __launch_bounds__(256) k_mlp(
    const float* __restrict__ g2, const float* __restrict__ b2,
    const float* __restrict__ f1w, const float* __restrict__ f1b,
    const float* __restrict__ f2w, const float* __restrict__ f2b) {
    extern __shared__ float sm[];
    float* Xs = sm;                 // 64 x 132
    float* Hs = sm + 64 * 132;      // 64 x 516
    float* Ws = Hs + 64 * 516;      // 64 x 132
    int tid = threadIdx.x;
    float* base = g_t + (size_t)blockIdx.x * 64 * 128;
#pragma unroll 4
    for (int r = 0; r < 32; r++) {
        int idx = tid + 256 * r;
        Xs[(idx >> 7) * 132 + (idx & 127)] = base[idx];
    }
    __syncthreads();
    // LN2 in place
    {
        int i = tid >> 2, l = tid & 3;
        float s = 0.0f, q = 0.0f;
#pragma unroll
        for (int c = l * 32; c < l * 32 + 32; c++) { float v = Xs[i * 132 + c]; s += v; q += v * v; }
        s += __shfl_xor_sync(0xffffffffu, s, 1); s += __shfl_xor_sync(0xffffffffu, s, 2);
        q += __shfl_xor_sync(0xffffffffu, q, 1); q += __shfl_xor_sync(0xffffffffu, q, 2);
        float mu   = s * (1.0f / 128.0f);
        float rstd = rsqrtf(q * (1.0f / 128.0f) - mu * mu + 1e-5f);
#pragma unroll
        for (int c = l * 32; c < l * 32 + 32; c++) {
            float v = Xs[i * 132 + c];
            Xs[i * 132 + c] = (v - mu) * rstd * g2[c] + b2[c];
        }
    }
    __syncthreads();

    int tg = tid >> 4, fl = tid & 15;
    const float* Xrow = Xs + 4 * tg * 132;

    // fc1 + gelu: 8 blocks of 64 features
#pragma unroll 1
    for (int blk = 0; blk < 8; blk++) {
        load_w_tile(Ws, f1w + blk * 64 * 128, 128, tid);
        __syncthreads();
        u64 acc[4][4] = {};
        gemm_tile<132, 132>(Xrow, Ws, fl, acc);
#pragma unroll
        for (int t = 0; t < 4; t++)
#pragma unroll
            for (int j = 0; j < 4; j++) {
                int f = blk * 64 + fl + 16 * j;
                Hs[(4 * tg + t) * 516 + f] = gelu_exact(f2sum(acc[t][j]) + f1b[f]);
            }
        __syncthreads();
    }

    // fc2 + residual: 2 feature blocks x 4 channel chunks
    const float* Hrow = Hs + 4 * tg * 516;
#pragma unroll 1
    for (int fblk = 0; fblk < 2; fblk++) {
        u64 acc[4][4] = {};
#pragma unroll 1
        for (int cblk = 0; cblk < 4; cblk++) {
            load_w_tile(Ws, f2w + (fblk * 64) * 512 + cblk * 128, 512, tid);
            __syncthreads();
            gemm_tile<516, 132>(Hrow + cblk * 128, Ws, fl, acc);
            __syncthreads();
        }
#pragma unroll
        for (int t = 0; t < 4; t++)
#pragma unroll
            for (int j = 0; j < 4; j++) {
                int f = fblk * 64 + fl + 16 * j;
                base[(4 * tg + t) * 128 + f] += f2sum(acc[t][j]) + f2b[f];
            }
    }
}

// ---------------- depthwise 3x3x3 conv: g_t -> g_w ----------------
__global__ void k_dw(const float* __restrict__ w, const float* __restrict__ bias) {
    __shared__ float ws[128 * 27];
    int tid = threadIdx.x;
    for (int idx = tid; idx < 128 * 27; idx += 128) ws[idx] = w[idx];
    __syncthreads();
    int c = tid;
    float bv = bias[c];
    int rid = blockIdx.x;
    int bb = rid >> 10, hh = (rid >> 5) & 31, ww = rid & 31;
    const float* base = g_t + (size_t)bb * 32768 * 128;
    float* out = g_w + ((size_t)bb * 32768 + hh * 1024 + ww * 32) * 128;
    for (int tt = 0; tt < 32; tt++) {
        float acc = bv;
#pragma unroll
        for (int dh = -1; dh <= 1; dh++) {
            int h2 = hh + dh; if ((unsigned)h2 >= 32u) continue;
#pragma unroll
            for (int dw_ = -1; dw_ <= 1; dw_++) {
                int w2 = ww + dw_; if ((unsigned)w2 >= 32u) continue;
#pragma unroll
                for (int dt = -1; dt <= 1; dt++) {
                    int t2 = tt + dt; if ((unsigned)t2 >= 32u) continue;
                    acc = fmaf(base[(h2 * 1024 + w2 * 32 + t2) * 128 + c],
                               ws[c * 27 + (dh + 1) * 9 + (dw_ + 1) * 3 + (dt + 1)], acc);
                }
            }
        }
        out[tt * 128 + c] = acc;
    }
}

// ---------------- pointwise conv 128->256 GEMM + BN partials ----------------
__global__ void __launch_bounds__(256) k_pw(
    const float* __restrict__ w, const float* __restrict__ bias,
    float* __restrict__ out) {
    extern __shared__ float sm[];
    float* Xs = sm;                 // 64 x 132
    float* Zs = sm + 64 * 132;      // 64 x 261
    float* Ws = Zs + 64 * 261;      // 64 x 132
    int tid = threadIdx.x;
    const float* base = g_w + (size_t)blockIdx.x * 64 * 128;
#pragma unroll 4
    for (int r = 0; r < 32; r++) {
        int idx = tid + 256 * r;
        Xs[(idx >> 7) * 132 + (idx & 127)] = base[idx];
    }
    __syncthreads();
    int tg = tid >> 4, fl = tid & 15;
    const float* Xrow = Xs + 4 * tg * 132;
#pragma unroll 1
    for (int blk = 0; blk < 4; blk++) {
        load_w_tile(Ws, w + blk * 64 * 128, 128, tid);
        __syncthreads();
        u64 acc[4][4] = {};
        gemm_tile<132, 132>(Xrow, Ws, fl, acc);
#pragma unroll
        for (int t = 0; t < 4; t++)
#pragma unroll
            for (int j = 0; j < 4; j++) {
                int f = blk * 64 + fl + 16 * j;
                Zs[(4 * tg + t) * 261 + f] = f2sum(acc[t][j]) + bias[f];
            }
        __syncthreads();
    }
    // coalesced store to out[b, o, p]
    {
        int warp = tid >> 5, lane = tid & 31;
        int token0 = blockIdx.x * 64;
        int bb = token0 >> 15, p0 = token0 & 32767;
        for (int o = warp; o < 256; o += 8) {
            float* op = out + (size_t)(bb * 256 + o) * 32768 + p0;
            op[lane]      = Zs[lane * 261 + o];
            op[lane + 32] = Zs[(lane + 32) * 261 + o];
        }
    }
    // deterministic per-CTA partial sums for BN
    {
        int o = tid;
        float s1 = 0.0f, s2 = 0.0f;
#pragma unroll 4
        for (int i = 0; i < 64; i++) { float z = Zs[i * 261 + o]; s1 += z; s2 += z * z; }
        g_psum[blockIdx.x * 256 + o] = s1;
        g_psqr[blockIdx.x * 256 + o] = s2;
    }
}

// ---------------- BN stats reduce ----------------
__global__ void k_bnred(const float* __restrict__ bng, const float* __restrict__ bnb) {
    int o = threadIdx.x;
    float s1 = 0.0f, s2 = 0.0f;
    for (int j = 0; j < 1024; j++) { s1 += g_psum[j * 256 + o]; s2 += g_psqr[j * 256 + o]; }
    float mu  = s1 * (1.0f / 65536.0f);
    float var = s2 * (1.0f / 65536.0f) - mu * mu;
    float sc  = bng[o] * rsqrtf(var + 1e-5f);
    g_bnsc[o] = sc;
    g_bnsh[o] = bnb[o] - mu * sc;
}

// ---------------- BN apply + ReLU ----------------
__global__ void k_bnap(float* __restrict__ out) {
    int idx4 = blockIdx.x * 256 + threadIdx.x;
    int o = ((idx4 * 4) >> 15) & 255;
    float sc = g_bnsc[o], sh = g_bnsh[o];
    float4 v = ((float4*)out)[idx4];
    v.x = fmaxf(v.x * sc + sh, 0.0f);
    v.y = fmaxf(v.y * sc + sh, 0.0f);
    v.z = fmaxf(v.z * sc + sh, 0.0f);
    v.w = fmaxf(v.w * sc + sh, 0.0f);
    ((float4*)out)[idx4] = v;
}

// ---------------- host launch ----------------
extern "C" void kernel_launch(void* const* d_in, const int* in_sizes, int n_in,
                              void* d_out, int out_size) {
    const float* x       = (const float*)d_in[0];
    const float* norm1_g = (const float*)d_in[1];
    const float* norm1_b = (const float*)d_in[2];
    const float* qkv_w   = (const float*)d_in[3];
    const float* qkv_b   = (const float*)d_in[4];
    const float* proj_w  = (const float*)d_in[5];
    const float* proj_b  = (const float*)d_in[6];
    const float* rpb     = (const float*)d_in[7];
    const float* norm2_g = (const float*)d_in[8];
    const float* norm2_b = (const float*)d_in[9];
    const float* fc1_w   = (const float*)d_in[10];
    const float* fc1_b   = (const float*)d_in[11];
    const float* fc2_w   = (const float*)d_in[12];
    const float* fc2_b   = (const float*)d_in[13];
    const float* dw_w    = (const float*)d_in[14];
    const float* dw_b    = (const float*)d_in[15];
    const float* pw_w    = (const float*)d_in[16];
    const float* pw_b    = (const float*)d_in[17];
    const float* bn_g    = (const float*)d_in[18];
    const float* bn_b    = (const float*)d_in[19];
    float* out = (float*)d_out;

    const int ASM = 5 * 64 * 132 * 4;                                   // 168960
    const int MSM = 64 * 132 * 4 + 64 * 516 * 4 + 64 * 132 * 4;         // 199680
    const int PSM = 64 * 132 * 4 + 64 * 261 * 4 + 64 * 132 * 4;         // 134400
    cudaFuncSetAttribute(k_attn, cudaFuncAttributeMaxDynamicSharedMemorySize, ASM);
    cudaFuncSetAttribute(k_mlp,  cudaFuncAttributeMaxDynamicSharedMemorySize, MSM);
    cudaFuncSetAttribute(k_pw,   cudaFuncAttributeMaxDynamicSharedMemorySize, PSM);

    k_tin<<<dim3(1024, 8), dim3(32, 8)>>>(x);

    for (int l = 0; l < 4; l++) {
        int shift = (l & 1) ? 2 : 0;
        k_ln_part<<<8192, 256>>>(norm1_g + l * 128, norm1_b + l * 128, shift);
        k_attn<<<1024, 256, ASM>>>(qkv_w + l * 384 * 128, qkv_b + l * 384,
                                   proj_w + l * 128 * 128, proj_b + l * 128,
                                   rpb + l * 343 * 8, shift);
        k_mlp<<<1024, 256, MSM>>>(norm2_g + l * 128, norm2_b + l * 128,
                                  fc1_w + l * 512 * 128, fc1_b + l * 512,
                                  fc2_w + l * 128 * 512, fc2_b + l * 128);
    }

    k_dw<<<2048, 128>>>(dw_w, dw_b);
    k_pw<<<1024, 256, PSM>>>(pw_w, pw_b, out);
    k_bnred<<<1, 256>>>(bn_g, bn_b);
    k_bnap<<<16384, 256>>>(out);
}